// round 1
// baseline (speedup 1.0000x reference)
#include <cuda_runtime.h>

#define IMG_H 100
#define IMG_W 100
#define IMG_C 256
#define OUT_HW 7
#define C4 (IMG_C / 4)   // 64 float4 per channel row

// Each block of 256 threads processes 4 output cells (roi, oy, ox).
// 64 lanes per cell, each lane handles 4 channels via float4.
__global__ void __launch_bounds__(256, 8)
roi_crop_resize_kernel(const float* __restrict__ img,
                       const float* __restrict__ rois,
                       float* __restrict__ out,
                       int n_cells)
{
    int cell = blockIdx.x * 4 + (threadIdx.x >> 6);
    if (cell >= n_cells) return;
    int lane = threadIdx.x & 63;

    int ox  = cell % OUT_HW;
    int oy  = (cell / OUT_HW) % OUT_HW;
    int roi = cell / (OUT_HW * OUT_HW);

    const float* r = rois + roi * 5;
    float rb  = __ldg(r + 0);
    float rx1 = __ldg(r + 1);
    float ry1 = __ldg(r + 2);
    float rx2 = __ldg(r + 3);
    float ry2 = __ldg(r + 4);

    int b = (int)rb;

    // normalized coords exactly as reference: b[:,k] = roi[:,k]/scale
    float x1 = rx1 * (1.0f / IMG_W);
    float x2 = rx2 * (1.0f / IMG_W);
    float y1 = ry1 * (1.0f / IMG_H);
    float y2 = ry2 * (1.0f / IMG_H);

    // in_y = y1*(H-1) + oy * ((y2-y1)*(H-1)/(ch-1))
    float in_y = y1 * (float)(IMG_H - 1)
               + (float)oy * ((y2 - y1) * (float)(IMG_H - 1) / (float)(OUT_HW - 1));
    float in_x = x1 * (float)(IMG_W - 1)
               + (float)ox * ((x2 - x1) * (float)(IMG_W - 1) / (float)(OUT_HW - 1));

    float4* ocell = (float4*)out + (size_t)cell * C4 + lane;

    bool valid = (in_y >= 0.0f) && (in_y <= (float)(IMG_H - 1)) &&
                 (in_x >= 0.0f) && (in_x <= (float)(IMG_W - 1));
    if (!valid) {
        *ocell = make_float4(0.f, 0.f, 0.f, 0.f);
        return;
    }

    float fy = floorf(in_y);
    float fx = floorf(in_x);
    float ly = in_y - fy;
    float lx = in_x - fx;

    int ty = min(max((int)fy, 0), IMG_H - 1);
    int by = min(max((int)ceilf(in_y), 0), IMG_H - 1);
    int tx = min(max((int)fx, 0), IMG_W - 1);
    int bx = min(max((int)ceilf(in_x), 0), IMG_W - 1);

    const float4* base = (const float4*)img;
    int row_t = (b * IMG_H + ty) * IMG_W;
    int row_b = (b * IMG_H + by) * IMG_W;

    const float4* p_tl = base + (size_t)(row_t + tx) * C4 + lane;
    const float4* p_tr = base + (size_t)(row_t + bx) * C4 + lane;
    const float4* p_bl = base + (size_t)(row_b + tx) * C4 + lane;
    const float4* p_br = base + (size_t)(row_b + bx) * C4 + lane;

    float4 tl = __ldg(p_tl);
    float4 tr = __ldg(p_tr);
    float4 bl = __ldg(p_bl);
    float4 br = __ldg(p_br);

    float4 res;
    {
        // top = tl + (tr-tl)*lx ; bot = bl + (br-bl)*lx ; out = top + (bot-top)*ly
        float top, bot;
        top = tl.x + (tr.x - tl.x) * lx;
        bot = bl.x + (br.x - bl.x) * lx;
        res.x = top + (bot - top) * ly;
        top = tl.y + (tr.y - tl.y) * lx;
        bot = bl.y + (br.y - bl.y) * lx;
        res.y = top + (bot - top) * ly;
        top = tl.z + (tr.z - tl.z) * lx;
        bot = bl.z + (br.z - bl.z) * lx;
        res.z = top + (bot - top) * ly;
        top = tl.w + (tr.w - tl.w) * lx;
        bot = bl.w + (br.w - bl.w) * lx;
        res.w = top + (bot - top) * ly;
    }
    *ocell = res;
}

extern "C" void kernel_launch(void* const* d_in, const int* in_sizes, int n_in,
                              void* d_out, int out_size)
{
    const float* img  = (const float*)d_in[0];
    const float* rois = (const float*)d_in[1];
    float* out = (float*)d_out;

    int n_rois  = in_sizes[1] / 5;                  // 2000
    int n_cells = n_rois * OUT_HW * OUT_HW;         // 98000

    int grid = (n_cells + 3) / 4;                   // 4 cells per 256-thread block
    roi_crop_resize_kernel<<<grid, 256>>>(img, rois, out, n_cells);
}

// round 2
// speedup vs baseline: 1.1205x; 1.1205x over previous
#include <cuda_runtime.h>

#define IMG_H 100
#define IMG_W 100
#define IMG_C 256
#define OUT_HW 7
#define C4 (IMG_C / 4)   // 64 float4 per channel row

// 256-thread block handles 8 output cells. 32 lanes per cell; each lane
// handles 8 channels = 2 float4 per corner -> 8 independent LDG.128 in
// flight per thread (2x the MLP of the previous version).
// Output stored with __stcs (evict-first) so the 82MB feature map stays
// resident in the 126MB L2 across graph replays.
__global__ void __launch_bounds__(256, 8)
roi_crop_resize_kernel(const float* __restrict__ img,
                       const float* __restrict__ rois,
                       float* __restrict__ out,
                       int n_cells)
{
    int cell = blockIdx.x * 8 + (threadIdx.x >> 5);
    if (cell >= n_cells) return;
    int lane = threadIdx.x & 31;

    int ox  = cell % OUT_HW;
    int oy  = (cell / OUT_HW) % OUT_HW;
    int roi = cell / (OUT_HW * OUT_HW);

    const float* r = rois + roi * 5;
    float rb  = __ldg(r + 0);
    float rx1 = __ldg(r + 1);
    float ry1 = __ldg(r + 2);
    float rx2 = __ldg(r + 3);
    float ry2 = __ldg(r + 4);

    int b = (int)rb;

    // normalized coords exactly as reference: b[:,k] = roi[:,k]/scale
    float x1 = rx1 * (1.0f / IMG_W);
    float x2 = rx2 * (1.0f / IMG_W);
    float y1 = ry1 * (1.0f / IMG_H);
    float y2 = ry2 * (1.0f / IMG_H);

    // in_y = y1*(H-1) + oy * ((y2-y1)*(H-1)/(ch-1))
    float in_y = y1 * (float)(IMG_H - 1)
               + (float)oy * ((y2 - y1) * (float)(IMG_H - 1) / (float)(OUT_HW - 1));
    float in_x = x1 * (float)(IMG_W - 1)
               + (float)ox * ((x2 - x1) * (float)(IMG_W - 1) / (float)(OUT_HW - 1));

    float4* ocell = (float4*)out + (size_t)cell * C4 + lane;

    bool valid = (in_y >= 0.0f) && (in_y <= (float)(IMG_H - 1)) &&
                 (in_x >= 0.0f) && (in_x <= (float)(IMG_W - 1));
    if (!valid) {
        float4 z = make_float4(0.f, 0.f, 0.f, 0.f);
        __stcs(ocell, z);
        __stcs(ocell + 32, z);
        return;
    }

    float fy = floorf(in_y);
    float fx = floorf(in_x);
    float ly = in_y - fy;
    float lx = in_x - fx;

    int ty = min(max((int)fy, 0), IMG_H - 1);
    int by = min(max((int)ceilf(in_y), 0), IMG_H - 1);
    int tx = min(max((int)fx, 0), IMG_W - 1);
    int bx = min(max((int)ceilf(in_x), 0), IMG_W - 1);

    const float4* base = (const float4*)img;
    int row_t = (b * IMG_H + ty) * IMG_W;
    int row_b = (b * IMG_H + by) * IMG_W;

    const float4* p_tl = base + (size_t)(row_t + tx) * C4 + lane;
    const float4* p_tr = base + (size_t)(row_t + bx) * C4 + lane;
    const float4* p_bl = base + (size_t)(row_b + tx) * C4 + lane;
    const float4* p_br = base + (size_t)(row_b + bx) * C4 + lane;

    // 8 independent loads issued back-to-back for max MLP
    float4 tl0 = __ldg(p_tl);
    float4 tr0 = __ldg(p_tr);
    float4 bl0 = __ldg(p_bl);
    float4 br0 = __ldg(p_br);
    float4 tl1 = __ldg(p_tl + 32);
    float4 tr1 = __ldg(p_tr + 32);
    float4 bl1 = __ldg(p_bl + 32);
    float4 br1 = __ldg(p_br + 32);

    // lerp exactly as reference: top = tl + (tr-tl)*lx; out = top + (bot-top)*ly
    #define LERP1(TL, TR, BL, BR, RES)                        \
    {                                                          \
        float top = TL + (TR - TL) * lx;                       \
        float bot = BL + (BR - BL) * lx;                       \
        RES = top + (bot - top) * ly;                          \
    }

    float4 res0, res1;
    LERP1(tl0.x, tr0.x, bl0.x, br0.x, res0.x)
    LERP1(tl0.y, tr0.y, bl0.y, br0.y, res0.y)
    LERP1(tl0.z, tr0.z, bl0.z, br0.z, res0.z)
    LERP1(tl0.w, tr0.w, bl0.w, br0.w, res0.w)
    LERP1(tl1.x, tr1.x, bl1.x, br1.x, res1.x)
    LERP1(tl1.y, tr1.y, bl1.y, br1.y, res1.y)
    LERP1(tl1.z, tr1.z, bl1.z, br1.z, res1.z)
    LERP1(tl1.w, tr1.w, bl1.w, br1.w, res1.w)
    #undef LERP1

    __stcs(ocell, res0);
    __stcs(ocell + 32, res1);
}

extern "C" void kernel_launch(void* const* d_in, const int* in_sizes, int n_in,
                              void* d_out, int out_size)
{
    const float* img  = (const float*)d_in[0];
    const float* rois = (const float*)d_in[1];
    float* out = (float*)d_out;

    int n_rois  = in_sizes[1] / 5;                  // 2000
    int n_cells = n_rois * OUT_HW * OUT_HW;         // 98000

    int grid = (n_cells + 7) / 8;                   // 8 cells per 256-thread block
    roi_crop_resize_kernel<<<grid, 256>>>(img, rois, out, n_cells);
}

// round 4
// speedup vs baseline: 1.1597x; 1.0350x over previous
#include <cuda_runtime.h>

#define IMG_H 100
#define IMG_W 100
#define IMG_C 256
#define OUT_HW 7

// 256-bit global access with L2 eviction-priority hints (sm_103 requires
// v8.b32 for evict modifiers). Image = evict_last (keep 82MB resident in
// 126MB L2 across graph replays); output = evict_first (write stream must
// not displace the image).
__device__ __forceinline__ void ldg256_el(const float* p, float* v) {
    unsigned r0, r1, r2, r3, r4, r5, r6, r7;
    asm volatile("ld.global.nc.L2::evict_last.v8.b32 {%0,%1,%2,%3,%4,%5,%6,%7}, [%8];"
                 : "=r"(r0), "=r"(r1), "=r"(r2), "=r"(r3),
                   "=r"(r4), "=r"(r5), "=r"(r6), "=r"(r7)
                 : "l"(p));
    v[0] = __uint_as_float(r0); v[1] = __uint_as_float(r1);
    v[2] = __uint_as_float(r2); v[3] = __uint_as_float(r3);
    v[4] = __uint_as_float(r4); v[5] = __uint_as_float(r5);
    v[6] = __uint_as_float(r6); v[7] = __uint_as_float(r7);
}
__device__ __forceinline__ void stg256_ef(float* p, const float* v) {
    asm volatile("st.global.L2::evict_first.v8.b32 [%0], {%1,%2,%3,%4,%5,%6,%7,%8};"
                 :: "l"(p),
                    "r"(__float_as_uint(v[0])), "r"(__float_as_uint(v[1])),
                    "r"(__float_as_uint(v[2])), "r"(__float_as_uint(v[3])),
                    "r"(__float_as_uint(v[4])), "r"(__float_as_uint(v[5])),
                    "r"(__float_as_uint(v[6])), "r"(__float_as_uint(v[7]))
                 : "memory");
}

// 256-thread block handles 8 output cells. 32 lanes per cell; each lane
// handles 8 contiguous channels via one 256-bit access per corner.
__global__ void __launch_bounds__(256, 8)
roi_crop_resize_kernel(const float* __restrict__ img,
                       const float* __restrict__ rois,
                       float* __restrict__ out,
                       int n_cells)
{
    int cell = blockIdx.x * 8 + (threadIdx.x >> 5);
    if (cell >= n_cells) return;
    int lane = threadIdx.x & 31;

    int ox  = cell % OUT_HW;
    int oy  = (cell / OUT_HW) % OUT_HW;
    int roi = cell / (OUT_HW * OUT_HW);

    const float* r = rois + roi * 5;
    float rb  = __ldg(r + 0);
    float rx1 = __ldg(r + 1);
    float ry1 = __ldg(r + 2);
    float rx2 = __ldg(r + 3);
    float ry2 = __ldg(r + 4);

    int b = (int)rb;

    // normalized coords exactly as reference: b[:,k] = roi[:,k]/scale
    float x1 = rx1 * (1.0f / IMG_W);
    float x2 = rx2 * (1.0f / IMG_W);
    float y1 = ry1 * (1.0f / IMG_H);
    float y2 = ry2 * (1.0f / IMG_H);

    // in_y = y1*(H-1) + oy * ((y2-y1)*(H-1)/(ch-1))
    float in_y = y1 * (float)(IMG_H - 1)
               + (float)oy * ((y2 - y1) * (float)(IMG_H - 1) / (float)(OUT_HW - 1));
    float in_x = x1 * (float)(IMG_W - 1)
               + (float)ox * ((x2 - x1) * (float)(IMG_W - 1) / (float)(OUT_HW - 1));

    float* ocell = out + (size_t)cell * IMG_C + lane * 8;

    bool valid = (in_y >= 0.0f) && (in_y <= (float)(IMG_H - 1)) &&
                 (in_x >= 0.0f) && (in_x <= (float)(IMG_W - 1));
    if (!valid) {
        float z[8] = {0.f, 0.f, 0.f, 0.f, 0.f, 0.f, 0.f, 0.f};
        stg256_ef(ocell, z);
        return;
    }

    float fy = floorf(in_y);
    float fx = floorf(in_x);
    float ly = in_y - fy;
    float lx = in_x - fx;

    int ty = min(max((int)fy, 0), IMG_H - 1);
    int by = min(max((int)ceilf(in_y), 0), IMG_H - 1);
    int tx = min(max((int)fx, 0), IMG_W - 1);
    int bx = min(max((int)ceilf(in_x), 0), IMG_W - 1);

    int row_t = (b * IMG_H + ty) * IMG_W;
    int row_b = (b * IMG_H + by) * IMG_W;
    int ch = lane * 8;

    const float* p_tl = img + (size_t)(row_t + tx) * IMG_C + ch;
    const float* p_tr = img + (size_t)(row_t + bx) * IMG_C + ch;
    const float* p_bl = img + (size_t)(row_b + tx) * IMG_C + ch;
    const float* p_br = img + (size_t)(row_b + bx) * IMG_C + ch;

    // 4 independent 256-bit loads in flight
    float tl[8], tr[8], bl[8], br[8];
    ldg256_el(p_tl, tl);
    ldg256_el(p_tr, tr);
    ldg256_el(p_bl, bl);
    ldg256_el(p_br, br);

    // lerp exactly as reference: top = tl + (tr-tl)*lx; out = top + (bot-top)*ly
    float res[8];
    #pragma unroll
    for (int i = 0; i < 8; i++) {
        float top = tl[i] + (tr[i] - tl[i]) * lx;
        float bot = bl[i] + (br[i] - bl[i]) * lx;
        res[i] = top + (bot - top) * ly;
    }

    stg256_ef(ocell, res);
}

extern "C" void kernel_launch(void* const* d_in, const int* in_sizes, int n_in,
                              void* d_out, int out_size)
{
    const float* img  = (const float*)d_in[0];
    const float* rois = (const float*)d_in[1];
    float* out = (float*)d_out;

    int n_rois  = in_sizes[1] / 5;                  // 2000
    int n_cells = n_rois * OUT_HW * OUT_HW;         // 98000

    int grid = (n_cells + 7) / 8;                   // 8 cells per 256-thread block
    roi_crop_resize_kernel<<<grid, 256>>>(img, rois, out, n_cells);
}